// round 15
// baseline (speedup 1.0000x reference)
#include <cuda_runtime.h>
#include <cuda_bf16.h>
#include <cuda_fp16.h>
#include <cstdint>
#include <math.h>

// Problem dims
#define BATCH 2048
#define HDIM  512
#define TSTEP 128
#define VDIM  64
#define GDIM  2048   // 4*HDIM

// ---------------- scratch (device globals; no allocation allowed) ----------
__device__ float g_xg[BATCH * GDIM];                         // 16 MB  x_gates
__device__ float g_hs[(size_t)BATCH * TSTEP * HDIM];         // 512 MB hidden states (fp32)
// h as fp16, double buffered by t parity
__device__ __half g_hA[2][BATCH * HDIM];
// w_hh fp16, rearranged per N-block (by in 0..15): [16][128 rows][512 k],
// tile row r -> orig row (r>>5)*512 + by*32 + (r&31)
__device__ __half g_wB[16][128 * HDIM];
// producer flags: g_flag[bm][by] = number of completed steps by CTA (bm,by)
__device__ int g_flag[16][16];

// ---------------- packed f32x2 helpers (FFMA2 path) -------------------------
typedef unsigned long long ull;

__device__ __forceinline__ ull ffma2(ull a, ull b, ull c) {
    ull d;
    asm("fma.rn.f32x2 %0, %1, %2, %3;" : "=l"(d) : "l"(a), "l"(b), "l"(c));
    return d;
}
__device__ __forceinline__ ull pk2(float x, float y) {
    ull r;
    asm("mov.b64 %0, {%1, %2};" : "=l"(r) : "f"(x), "f"(y));
    return r;
}
__device__ __forceinline__ float2 up2(ull v) {
    float2 r;
    asm("mov.b64 {%0, %1}, %2;" : "=f"(r.x), "=f"(r.y) : "l"(v));
    return r;
}

__device__ __forceinline__ float sigm(float x) {
    return 1.0f / (1.0f + __expf(-x));
}
__device__ __forceinline__ float tanh_fast(float x) {
    float e = __expf(-2.0f * fabsf(x));
    float r = (1.0f - e) / (1.0f + e);
    return copysignf(r, x);
}

// streaming (evict-first) global access helpers
__device__ __forceinline__ void st_cs_f32(float* p, float v) {
    asm volatile("st.global.cs.f32 [%0], %1;" :: "l"(p), "f"(v) : "memory");
}
__device__ __forceinline__ float2 ld_cs_f32x2(const float* p) {
    float2 r;
    asm volatile("ld.global.cs.v2.f32 {%0, %1}, [%2];" : "=f"(r.x), "=f"(r.y) : "l"(p));
    return r;
}

// acquire/release flag ops
__device__ __forceinline__ int ld_acq(const int* p) {
    int v;
    asm volatile("ld.acquire.gpu.global.s32 %0, [%1];" : "=r"(v) : "l"(p) : "memory");
    return v;
}
__device__ __forceinline__ void st_rel(int* p, int v) {
    asm volatile("st.release.gpu.global.s32 [%0], %1;" :: "l"(p), "r"(v) : "memory");
}

// ---------------- mma.sync / ldmatrix / cp.async helpers --------------------
__device__ __forceinline__ uint32_t smem_u32(const void* p) {
    uint32_t a;
    asm("{ .reg .u64 t; cvta.to.shared.u64 t, %1; cvt.u32.u64 %0, t; }" : "=r"(a) : "l"(p));
    return a;
}
__device__ __forceinline__ void ldsm_x4(uint32_t* r, uint32_t addr) {
    asm volatile("ldmatrix.sync.aligned.m8n8.x4.shared.b16 {%0,%1,%2,%3}, [%4];"
                 : "=r"(r[0]), "=r"(r[1]), "=r"(r[2]), "=r"(r[3]) : "r"(addr));
}
// fp16 MMA m16n8k16, f32 accum
__device__ __forceinline__ void mma16816h(float* d, const uint32_t* a, const uint32_t* b) {
    asm volatile("mma.sync.aligned.m16n8k16.row.col.f32.f16.f16.f32 "
                 "{%0,%1,%2,%3}, {%4,%5,%6,%7}, {%8,%9}, {%0,%1,%2,%3};"
                 : "+f"(d[0]), "+f"(d[1]), "+f"(d[2]), "+f"(d[3])
                 : "r"(a[0]), "r"(a[1]), "r"(a[2]), "r"(a[3]), "r"(b[0]), "r"(b[1]));
}
__device__ __forceinline__ void cpa16(uint32_t dst, const void* src) {
    asm volatile("cp.async.cg.shared.global [%0], [%1], 16;"
                 :: "r"(dst), "l"(__cvta_generic_to_global(src)) : "memory");
}
#define CPA_COMMIT() asm volatile("cp.async.commit_group;" ::: "memory")
#define CPA_WAIT0()  asm volatile("cp.async.wait_group 0;" ::: "memory")
#define CPA_WAIT1()  asm volatile("cp.async.wait_group 1;" ::: "memory")

// ---------------- init: zero h0 and flags --------------------------------
__global__ void init_kernel() {
    int i = blockIdx.x * blockDim.x + threadIdx.x;
    if (i < 256) ((int*)g_flag)[i] = 0;
    if (i < BATCH * HDIM) g_hA[0][i] = __float2half(0.0f);
}

// ---------------- wprep: fp16 convert + rearrange w_hh -----------------------
__global__ void wprep_kernel(const float* __restrict__ w_hh) {
    int i = blockIdx.x * blockDim.x + threadIdx.x;   // over 16*128*512
    if (i >= 16 * 128 * HDIM) return;
    int k = i & (HDIM - 1);
    int r = (i >> 9) & 127;
    int by = i >> 16;
    int orig_row = ((r >> 5) << 9) + by * 32 + (r & 31);
    g_wB[by][r * HDIM + k] = __float2half_rn(w_hh[(size_t)orig_row * HDIM + k]);
}

// -------- pre: x_gates = z @ w_ih.T + b_ih + b_hh (FFMA2, one-time) ----------
__global__ __launch_bounds__(256, 2)
void pre_kernel(const float* __restrict__ z,
                const float* __restrict__ w_ih,
                const float* __restrict__ b_ih,
                const float* __restrict__ b_hh) {
    __shared__ float As[16][132];
    __shared__ float Bs[16][130];

    const int bm = blockIdx.x;
    const int j0 = blockIdx.y * 32;
    const int tid = threadIdx.x;
    const int tr = tid >> 4, tc = tid & 15;
    const int jj0 = tc * 2;

    ull acc[8][4];
#pragma unroll
    for (int i = 0; i < 8; i++)
#pragma unroll
        for (int g = 0; g < 4; g++) acc[i][g] = 0ull;

    for (int k0 = 0; k0 < HDIM; k0 += 16) {
#pragma unroll
        for (int it = 0; it < 2; it++) {
            int i = tid + it * 256;
            int row = i >> 2, kq = (i & 3) * 4;
            float4 va = *(const float4*)(z + (size_t)(bm * 128 + row) * HDIM + k0 + kq);
            As[kq + 0][row] = va.x; As[kq + 1][row] = va.y;
            As[kq + 2][row] = va.z; As[kq + 3][row] = va.w;
            int n = row;
            int gcol = ((n >> 5) << 9) + j0 + (n & 31);
            float4 vb = *(const float4*)(w_ih + (size_t)gcol * HDIM + k0 + kq);
            Bs[kq + 0][n] = vb.x; Bs[kq + 1][n] = vb.y;
            Bs[kq + 2][n] = vb.z; Bs[kq + 3][n] = vb.w;
        }
        __syncthreads();
#pragma unroll
        for (int kk = 0; kk < 16; kk++) {
            float4 a0 = *(const float4*)&As[kk][tr * 8];
            float4 a1 = *(const float4*)&As[kk][tr * 8 + 4];
            ull b0 = *(const ull*)&Bs[kk][jj0];
            ull b1 = *(const ull*)&Bs[kk][32 + jj0];
            ull b2 = *(const ull*)&Bs[kk][64 + jj0];
            ull b3 = *(const ull*)&Bs[kk][96 + jj0];
            float av[8] = {a0.x, a0.y, a0.z, a0.w, a1.x, a1.y, a1.z, a1.w};
#pragma unroll
            for (int i = 0; i < 8; i++) {
                ull ad = pk2(av[i], av[i]);
                acc[i][0] = ffma2(ad, b0, acc[i][0]);
                acc[i][1] = ffma2(ad, b1, acc[i][1]);
                acc[i][2] = ffma2(ad, b2, acc[i][2]);
                acc[i][3] = ffma2(ad, b3, acc[i][3]);
            }
        }
        __syncthreads();
    }

    const int b0r = bm * 128 + tr * 8;
#pragma unroll
    for (int i = 0; i < 8; i++) {
        int b = b0r + i;
        float2 vv[4];
#pragma unroll
        for (int g = 0; g < 4; g++) vv[g] = up2(acc[i][g]);
#pragma unroll
        for (int g = 0; g < 4; g++) {
            int c0 = g * 512 + j0 + jj0;
            g_xg[(size_t)b * GDIM + c0]     = vv[g].x + b_ih[c0]     + b_hh[c0];
            g_xg[(size_t)b * GDIM + c0 + 1] = vv[g].y + b_ih[c0 + 1] + b_hh[c0 + 1];
        }
    }
}

// ============================================================================
// step_persist: ALL 128 timesteps in one persistent kernel.
//   grid 256 CTAs (2/SM, all co-resident), 256 threads, CTA keeps tile (bm,by).
//   DATAFLOW SYNC: chunk c of CTA (bm,*) depends only on CTAs (bm, 2c) and
//   (bm, 2c+1). Per-CTA monotone flags replace the global barrier: the 16
//   bm-groups run fully decoupled, and within a group each CTA starts the next
//   step's loads as soon as the producing pair has finished its epilogue.
// ============================================================================
#define KCH 64
#define B_OFF 16384
#define BUFSZ 32768
#define NBUF  3
#define CS_OFF (NBUF * BUFSZ)                 // 98304
#define EPI_STRIDE 132
#define SMEM_TOTAL (CS_OFF + 16384)           // 114688 (x2 CTA = 229376 <= 233472)
#define NCTA 256

__global__ __launch_bounds__(256, 2)
void step_persist() {
    extern __shared__ char smem[];
    const uint32_t smem_base = smem_u32(smem);
    float* E = (float*)smem;                       // epilogue staging (reuses op bufs)
    float* cS = (float*)(smem + CS_OFF);           // c state [16][256]

    const int tid = threadIdx.x;
    const int wid = tid >> 5;
    const int lid = tid & 31;
    const int bm = blockIdx.x >> 4;
    const int by = blockIdx.x & 15;

    const __half* __restrict__ wb = g_wB[by];

    // zero c state
#pragma unroll
    for (int i = 0; i < 16; i++) cS[i * 256 + tid] = 0.0f;

    // ---- ldmatrix lane address components (128B rows, 8 16B-units) ----
    const int warp_m = wid >> 2;           // 0..1 -> m base warp_m*64
    const int warp_n = wid & 3;            // 0..3 -> n base warp_n*32 (= gate)
    const int j = lid >> 3;
    const int kha = j >> 1;
    const int khb = j & 1;
    uint32_t aB[4]; int a7[4];
    uint32_t bB[2]; int b7[2];
    {
        int ra = warp_m * 64 + (lid & 7) + ((j & 1) << 3);
#pragma unroll
        for (int i = 0; i < 4; i++) {
            int row = ra + i * 16;
            aB[i] = row * 128; a7[i] = row & 7;
        }
        int rb = warp_n * 32 + (lid & 7) + (((lid >> 4) & 1) << 3);
#pragma unroll
        for (int q = 0; q < 2; q++) {
            int row = rb + q * 16;
            bB[q] = row * 128; b7[q] = row & 7;
        }
    }

    // epilogue thread mapping (fixed across steps)
    const int hl = tid & 31;
    const int mw = (tid >> 5) * 8;
    const int hcol_g = by * 32 + hl;

    // fragment double buffer + accumulators
    uint32_t af[2][4][4], bf[2][2][4];
    float acc[4][4][4];

#define ISSUE_CP(HIN, CH, BI) do {                                              \
    const uint32_t _bo = (BI) * BUFSZ;                                          \
    const uint32_t _ko = (CH) * KCH;                                            \
    _Pragma("unroll")                                                           \
    for (int _it = 0; _it < 4; _it++) {                                         \
        int _q = tid + _it * 256;                                               \
        int _r = _q >> 3, _u = _q & 7;                                          \
        uint32_t _dst = smem_base + _bo + _r * 128 + (((_u ^ (_r & 7))) << 4);  \
        cpa16(_dst, (HIN) + (uint32_t)(bm * 128 + _r) * HDIM + _ko + _u * 8);   \
        cpa16(_dst + B_OFF, wb + (uint32_t)_r * HDIM + _ko + _u * 8);           \
    }                                                                           \
} while (0)

// wait until producers of chunk CH (CTAs (bm,2CH) and (bm,2CH+1)) reach step T
#define WAIT_FLAGS(T, CH) do {                                                  \
    const int* _f = &g_flag[bm][2 * (CH)];                                      \
    while (ld_acq(_f)     < (T)) __nanosleep(32);                               \
    while (ld_acq(_f + 1) < (T)) __nanosleep(32);                               \
} while (0)

#define LOADF(P, BASE, S) do {                                                  \
    const uint32_t _ua = 2 * (S) + kha;                                         \
    const uint32_t _ub = 2 * (S) + khb;                                         \
    _Pragma("unroll")                                                           \
    for (int _i = 0; _i < 4; _i++)                                              \
        ldsm_x4(af[P][_i], (BASE) + aB[_i] + ((_ua ^ a7[_i]) << 4));            \
    _Pragma("unroll")                                                           \
    for (int _q = 0; _q < 2; _q++)                                              \
        ldsm_x4(bf[P][_q], (BASE) + B_OFF + bB[_q] + ((_ub ^ b7[_q]) << 4));    \
} while (0)

#define MMA16(P) do {                                                           \
    _Pragma("unroll")                                                           \
    for (int _i = 0; _i < 4; _i++)                                              \
        _Pragma("unroll")                                                       \
        for (int _f = 0; _f < 4; _f++)                                          \
            mma16816h(acc[_i][_f], af[P][_i], &bf[P][_f >> 1][(_f & 1) * 2]);   \
} while (0)

    __syncthreads();

    for (int t = 0; t < TSTEP; t++) {
        const __half* __restrict__ hin = g_hA[t & 1];
        __half* __restrict__ hout = g_hA[(t & 1) ^ 1];

#pragma unroll
        for (int i = 0; i < 4; i++)
#pragma unroll
            for (int f = 0; f < 4; f++)
#pragma unroll
                for (int v = 0; v < 4; v++) acc[i][f][v] = 0.0f;

        // prologue: chunks 0, 1 (each gated on its producer pair)
        WAIT_FLAGS(t, 0);
        ISSUE_CP(hin, 0, 0); CPA_COMMIT();
        WAIT_FLAGS(t, 1);
        ISSUE_CP(hin, 1, 1); CPA_COMMIT();
        CPA_WAIT1();
        __syncthreads();
        LOADF(0, smem_base, 0);

        int buf = 0;
        for (int c = 0; c < 8; c++) {
            if (c <= 5) {
                WAIT_FLAGS(t, c + 2);
                ISSUE_CP(hin, c + 2, (c + 2) % NBUF); CPA_COMMIT();
            }
            const uint32_t base = smem_base + buf * BUFSZ;
            // s = 0 (frags already in P=0)
            LOADF(1, base, 1);
            MMA16(0);
            // s = 1
            LOADF(0, base, 2);
            MMA16(1);
            // s = 2
            LOADF(1, base, 3);
            MMA16(0);
            // s = 3 -> overlap with next buffer's first load
            if (c <= 5)      { CPA_WAIT1(); __syncthreads(); }
            else if (c == 6) { CPA_WAIT0(); __syncthreads(); }
            buf = (buf + 1 == NBUF) ? 0 : buf + 1;
            if (c < 7) LOADF(0, smem_base + buf * BUFSZ, 0);
            MMA16(1);
        }

        // ---- epilogue: two 64-row halves; xg from global (L2), c in SMEM ----
        __syncthreads();
#pragma unroll
        for (int half = 0; half < 2; half++) {
            if (warp_m == half) {
                const int rl = (lid >> 2);
                const int c0 = warp_n * 32 + (lid & 3) * 2;
#pragma unroll
                for (int i = 0; i < 4; i++)
#pragma unroll
                    for (int f = 0; f < 4; f++) {
                        int r = rl + i * 16;
                        int cc = c0 + f * 8;
                        *(float2*)&E[r * EPI_STRIDE + cc]       = make_float2(acc[i][f][0], acc[i][f][1]);
                        *(float2*)&E[(r + 8) * EPI_STRIDE + cc] = make_float2(acc[i][f][2], acc[i][f][3]);
                    }
            }
            __syncthreads();
#pragma unroll 4
            for (int jj = 0; jj < 8; jj++) {
                const int ml = mw + jj;
                const int m = half * 64 + ml;
                const int b = bm * 128 + m;
                const float* xr = g_xg + (size_t)b * GDIM + hcol_g;
                float gi = E[ml * EPI_STRIDE + hl]      + xr[0];
                float gf = E[ml * EPI_STRIDE + 32 + hl] + xr[512];
                float gg = E[ml * EPI_STRIDE + 64 + hl] + xr[1024];
                float go = E[ml * EPI_STRIDE + 96 + hl] + xr[1536];
                float cold = cS[(half * 8 + jj) * 256 + tid];
                float cn = sigm(gf) * cold + sigm(gi) * tanh_fast(gg);
                cS[(half * 8 + jj) * 256 + tid] = cn;
                float hn = sigm(go) * tanh_fast(cn);
                st_cs_f32(g_hs + ((size_t)b * TSTEP + t) * HDIM + hcol_g, hn);
                hout[(size_t)b * HDIM + hcol_g] = __float2half_rn(hn);
            }
            __syncthreads();
        }

        // ---- publish: this CTA's h(t+1) columns are globally visible ----
        __threadfence();
        __syncthreads();
        if (tid == 0) st_rel(&g_flag[bm][by], t + 1);
    }
#undef ISSUE_CP
#undef WAIT_FLAGS
#undef LOADF
#undef MMA16
}

// -------- fc: out = relu(hs @ fc_w.T + fc_b) --------------------------------
__global__ __launch_bounds__(256)
void fc_kernel(const float* __restrict__ fc_w,
               const float* __restrict__ fc_b,
               float* __restrict__ out) {
    __shared__ float hsS[16][514];
    const size_t row0 = (size_t)blockIdx.x * 16;
    const int tid = threadIdx.x;

#pragma unroll
    for (int it = 0; it < 16; it++) {
        int i = tid + it * 256;
        int row = i >> 8;
        int cc = (i & 255) * 2;
        float2 v = ld_cs_f32x2(g_hs + (row0 + row) * HDIM + cc);
        *(float2*)&hsS[row][cc] = v;
    }
    __syncthreads();

    const int r = tid & 15;
    const int v0 = (tid >> 4) * 4;
    ull acc[4] = {0ull, 0ull, 0ull, 0ull};
    const float* w0 = fc_w + (size_t)v0 * HDIM;

#pragma unroll 8
    for (int k = 0; k < HDIM; k += 2) {
        ull a = *(const ull*)&hsS[r][k];
        acc[0] = ffma2(a, *(const ull*)(w0 + k),        acc[0]);
        acc[1] = ffma2(a, *(const ull*)(w0 + 512 + k),  acc[1]);
        acc[2] = ffma2(a, *(const ull*)(w0 + 1024 + k), acc[2]);
        acc[3] = ffma2(a, *(const ull*)(w0 + 1536 + k), acc[3]);
    }
#pragma unroll
    for (int jj = 0; jj < 4; jj++) {
        float2 s = up2(acc[jj]);
        float v = s.x + s.y + fc_b[v0 + jj];
        out[(row0 + r) * VDIM + v0 + jj] = fmaxf(v, 0.0f);
    }
}

// ---------------- launch ----------------------------------------------------
extern "C" void kernel_launch(void* const* d_in, const int* in_sizes, int n_in,
                              void* d_out, int out_size) {
    const float* z    = (const float*)d_in[0];
    const float* w_ih = (const float*)d_in[1];
    const float* w_hh = (const float*)d_in[2];
    const float* b_ih = (const float*)d_in[3];
    const float* b_hh = (const float*)d_in[4];
    const float* fc_w = (const float*)d_in[5];
    const float* fc_b = (const float*)d_in[6];
    float* out = (float*)d_out;

    cudaFuncSetAttribute(step_persist, cudaFuncAttributeMaxDynamicSharedMemorySize, SMEM_TOTAL);

    init_kernel<<<(BATCH * HDIM + 255) / 256, 256>>>();
    wprep_kernel<<<(16 * 128 * HDIM + 255) / 256, 256>>>(w_hh);
    pre_kernel<<<dim3(16, 16), 256>>>(z, w_ih, b_ih, b_hh);
    step_persist<<<NCTA, 256, SMEM_TOTAL>>>();
    fc_kernel<<<(BATCH * TSTEP) / 16, 256>>>(fc_w, fc_b, out);
}

// round 16
// speedup vs baseline: 1.2680x; 1.2680x over previous
#include <cuda_runtime.h>
#include <cuda_bf16.h>
#include <cuda_fp16.h>
#include <cstdint>
#include <math.h>

// Problem dims
#define BATCH 2048
#define HDIM  512
#define TSTEP 128
#define VDIM  64
#define GDIM  2048   // 4*HDIM

// ---------------- scratch (device globals; no allocation allowed) ----------
__device__ float g_xg[BATCH * GDIM];                         // 16 MB  x_gates
__device__ float g_hs[(size_t)BATCH * TSTEP * HDIM];         // 512 MB hidden states (fp32)
// h as fp16, double buffered by t parity
__device__ __half g_hA[2][BATCH * HDIM];
// w_hh fp16, rearranged per N-block (by in 0..15): [16][128 rows][512 k],
// tile row r -> orig row (r>>5)*512 + by*32 + (r&31)
__device__ __half g_wB[16][128 * HDIM];
// grid barrier counter
__device__ unsigned g_bar;

// ---------------- packed f32x2 helpers (FFMA2 path) -------------------------
typedef unsigned long long ull;

__device__ __forceinline__ ull ffma2(ull a, ull b, ull c) {
    ull d;
    asm("fma.rn.f32x2 %0, %1, %2, %3;" : "=l"(d) : "l"(a), "l"(b), "l"(c));
    return d;
}
__device__ __forceinline__ ull pk2(float x, float y) {
    ull r;
    asm("mov.b64 %0, {%1, %2};" : "=l"(r) : "f"(x), "f"(y));
    return r;
}
__device__ __forceinline__ float2 up2(ull v) {
    float2 r;
    asm("mov.b64 {%0, %1}, %2;" : "=f"(r.x), "=f"(r.y) : "l"(v));
    return r;
}

__device__ __forceinline__ float sigm(float x) {
    return 1.0f / (1.0f + __expf(-x));
}
__device__ __forceinline__ float tanh_fast(float x) {
    float e = __expf(-2.0f * fabsf(x));
    float r = (1.0f - e) / (1.0f + e);
    return copysignf(r, x);
}

// streaming (evict-first) global access helpers
__device__ __forceinline__ void st_cs_f32x2(float* p, float x, float y) {
    asm volatile("st.global.cs.v2.f32 [%0], {%1, %2};" :: "l"(p), "f"(x), "f"(y) : "memory");
}
__device__ __forceinline__ float2 ld_cs_f32x2(const float* p) {
    float2 r;
    asm volatile("ld.global.cs.v2.f32 {%0, %1}, [%2];" : "=f"(r.x), "=f"(r.y) : "l"(p));
    return r;
}

// ---------------- mma.sync / ldmatrix / cp.async helpers --------------------
__device__ __forceinline__ uint32_t smem_u32(const void* p) {
    uint32_t a;
    asm("{ .reg .u64 t; cvta.to.shared.u64 t, %1; cvt.u32.u64 %0, t; }" : "=r"(a) : "l"(p));
    return a;
}
__device__ __forceinline__ void ldsm_x4(uint32_t* r, uint32_t addr) {
    asm volatile("ldmatrix.sync.aligned.m8n8.x4.shared.b16 {%0,%1,%2,%3}, [%4];"
                 : "=r"(r[0]), "=r"(r[1]), "=r"(r[2]), "=r"(r[3]) : "r"(addr));
}
// fp16 MMA m16n8k16, f32 accum
__device__ __forceinline__ void mma16816h(float* d, const uint32_t* a, const uint32_t* b) {
    asm volatile("mma.sync.aligned.m16n8k16.row.col.f32.f16.f16.f32 "
                 "{%0,%1,%2,%3}, {%4,%5,%6,%7}, {%8,%9}, {%0,%1,%2,%3};"
                 : "+f"(d[0]), "+f"(d[1]), "+f"(d[2]), "+f"(d[3])
                 : "r"(a[0]), "r"(a[1]), "r"(a[2]), "r"(a[3]), "r"(b[0]), "r"(b[1]));
}
__device__ __forceinline__ void cpa16(uint32_t dst, const void* src) {
    asm volatile("cp.async.cg.shared.global [%0], [%1], 16;"
                 :: "r"(dst), "l"(__cvta_generic_to_global(src)) : "memory");
}
#define CPA_COMMIT() asm volatile("cp.async.commit_group;" ::: "memory")
#define CPA_WAIT0()  asm volatile("cp.async.wait_group 0;" ::: "memory")
#define CPA_WAIT1()  asm volatile("cp.async.wait_group 1;" ::: "memory")

// ---------------- init: zero h0 and barrier ----------------------------------
__global__ void init_kernel() {
    int i = blockIdx.x * blockDim.x + threadIdx.x;
    if (i == 0) g_bar = 0u;
    if (i < BATCH * HDIM) g_hA[0][i] = __float2half(0.0f);
}

// ---------------- wprep: fp16 convert + rearrange w_hh -----------------------
__global__ void wprep_kernel(const float* __restrict__ w_hh) {
    int i = blockIdx.x * blockDim.x + threadIdx.x;   // over 16*128*512
    if (i >= 16 * 128 * HDIM) return;
    int k = i & (HDIM - 1);
    int r = (i >> 9) & 127;
    int by = i >> 16;
    int orig_row = ((r >> 5) << 9) + by * 32 + (r & 31);
    g_wB[by][r * HDIM + k] = __float2half_rn(w_hh[(size_t)orig_row * HDIM + k]);
}

// -------- pre: x_gates = z @ w_ih.T + b_ih + b_hh (FFMA2, one-time) ----------
__global__ __launch_bounds__(256, 2)
void pre_kernel(const float* __restrict__ z,
                const float* __restrict__ w_ih,
                const float* __restrict__ b_ih,
                const float* __restrict__ b_hh) {
    __shared__ float As[16][132];
    __shared__ float Bs[16][130];

    const int bm = blockIdx.x;
    const int j0 = blockIdx.y * 32;
    const int tid = threadIdx.x;
    const int tr = tid >> 4, tc = tid & 15;
    const int jj0 = tc * 2;

    ull acc[8][4];
#pragma unroll
    for (int i = 0; i < 8; i++)
#pragma unroll
        for (int g = 0; g < 4; g++) acc[i][g] = 0ull;

    for (int k0 = 0; k0 < HDIM; k0 += 16) {
#pragma unroll
        for (int it = 0; it < 2; it++) {
            int i = tid + it * 256;
            int row = i >> 2, kq = (i & 3) * 4;
            float4 va = *(const float4*)(z + (size_t)(bm * 128 + row) * HDIM + k0 + kq);
            As[kq + 0][row] = va.x; As[kq + 1][row] = va.y;
            As[kq + 2][row] = va.z; As[kq + 3][row] = va.w;
            int n = row;
            int gcol = ((n >> 5) << 9) + j0 + (n & 31);
            float4 vb = *(const float4*)(w_ih + (size_t)gcol * HDIM + k0 + kq);
            Bs[kq + 0][n] = vb.x; Bs[kq + 1][n] = vb.y;
            Bs[kq + 2][n] = vb.z; Bs[kq + 3][n] = vb.w;
        }
        __syncthreads();
#pragma unroll
        for (int kk = 0; kk < 16; kk++) {
            float4 a0 = *(const float4*)&As[kk][tr * 8];
            float4 a1 = *(const float4*)&As[kk][tr * 8 + 4];
            ull b0 = *(const ull*)&Bs[kk][jj0];
            ull b1 = *(const ull*)&Bs[kk][32 + jj0];
            ull b2 = *(const ull*)&Bs[kk][64 + jj0];
            ull b3 = *(const ull*)&Bs[kk][96 + jj0];
            float av[8] = {a0.x, a0.y, a0.z, a0.w, a1.x, a1.y, a1.z, a1.w};
#pragma unroll
            for (int i = 0; i < 8; i++) {
                ull ad = pk2(av[i], av[i]);
                acc[i][0] = ffma2(ad, b0, acc[i][0]);
                acc[i][1] = ffma2(ad, b1, acc[i][1]);
                acc[i][2] = ffma2(ad, b2, acc[i][2]);
                acc[i][3] = ffma2(ad, b3, acc[i][3]);
            }
        }
        __syncthreads();
    }

    const int b0r = bm * 128 + tr * 8;
#pragma unroll
    for (int i = 0; i < 8; i++) {
        int b = b0r + i;
        float2 vv[4];
#pragma unroll
        for (int g = 0; g < 4; g++) vv[g] = up2(acc[i][g]);
#pragma unroll
        for (int g = 0; g < 4; g++) {
            int c0 = g * 512 + j0 + jj0;
            g_xg[(size_t)b * GDIM + c0]     = vv[g].x + b_ih[c0]     + b_hh[c0];
            g_xg[(size_t)b * GDIM + c0 + 1] = vv[g].y + b_ih[c0 + 1] + b_hh[c0 + 1];
        }
    }
}

// ============================================================================
// step_persist: ALL 128 timesteps in one persistent kernel.
//   grid 256 CTAs (2/SM, all co-resident), 256 threads, CTA keeps tile (bm,by).
//   GATE-INTERLEAVED B FRAGMENTS: ldmatrix.x4 lane-group addresses pick the
//   4 n8-tiles from the 4 gates (n = g*32 + wn*8), so each thread's
//   accumulators hold complete (i,f,g,o) quads -> the LSTM cell epilogue is
//   REGISTER-LOCAL (no SMEM staging, no extra syncthreads, all warps active).
//   c state: per-thread float2[8] in SMEM. Global barrier between steps.
// ============================================================================
#define KCH 64
#define B_OFF 16384
#define BUFSZ 32768
#define NBUF  3
#define CS_OFF (NBUF * BUFSZ)                 // 98304
#define SMEM_TOTAL (CS_OFF + 16384)           // 114688 (x2 CTA = 229376 <= 233472)
#define NCTA 256

__global__ __launch_bounds__(256, 2)
void step_persist() {
    extern __shared__ char smem[];
    const uint32_t smem_base = smem_u32(smem);
    float2* cS2 = (float2*)(smem + CS_OFF);        // c state [8][256] float2

    const int tid = threadIdx.x;
    const int wid = tid >> 5;
    const int lid = tid & 31;
    const int bm = blockIdx.x >> 4;
    const int by = blockIdx.x & 15;

    const __half* __restrict__ wb = g_wB[by];

    // zero c state
#pragma unroll
    for (int i = 0; i < 8; i++) cS2[i * 256 + tid] = make_float2(0.0f, 0.0f);

    // ---- ldmatrix lane address components (128B rows, 8 16B-units) ----
    const int warp_m = wid >> 2;           // 0..1 -> m base warp_m*64
    const int warp_n = wid & 3;            // 0..3 -> hcol-block wn*8
    const int j = lid >> 3;
    const int kha = j >> 1;                // A k-half select
    const int khb = j & 1;                 // B k-half select
    uint32_t aB[4]; int a7[4];
    uint32_t bB[2]; int b7[2];
    {
        int ra = warp_m * 64 + (lid & 7) + ((j & 1) << 3);
#pragma unroll
        for (int i = 0; i < 4; i++) {
            int row = ra + i * 16;
            aB[i] = row * 128; a7[i] = row & 7;
        }
        // gate-interleaved B rows: ldsm q covers gates 2q ((lid>>4)&1 = 0)
        // and 2q+1 ((lid>>4)&1 = 1); n-block = gate*32 + warp_n*8
#pragma unroll
        for (int q = 0; q < 2; q++) {
            int gate = 2 * q + ((lid >> 4) & 1);
            int row = gate * 32 + warp_n * 8 + (lid & 7);
            bB[q] = row * 128; b7[q] = row & 7;
        }
    }

    // epilogue thread mapping (register-local gates)
    const int rbase = warp_m * 64 + (lid >> 2);
    const int hcol_g = by * 32 + warp_n * 8 + (lid & 3) * 2;

    // fragment double buffer + accumulators
    uint32_t af[2][4][4], bf[2][2][4];
    float acc[4][4][4];   // acc[i][gate][v]

#define ISSUE_CP(HIN, CH, BI) do {                                              \
    const uint32_t _bo = (BI) * BUFSZ;                                          \
    const uint32_t _ko = (CH) * KCH;                                            \
    _Pragma("unroll")                                                           \
    for (int _it = 0; _it < 4; _it++) {                                         \
        int _q = tid + _it * 256;                                               \
        int _r = _q >> 3, _u = _q & 7;                                          \
        uint32_t _dst = smem_base + _bo + _r * 128 + (((_u ^ (_r & 7))) << 4);  \
        cpa16(_dst, (HIN) + (uint32_t)(bm * 128 + _r) * HDIM + _ko + _u * 8);   \
        cpa16(_dst + B_OFF, wb + (uint32_t)_r * HDIM + _ko + _u * 8);           \
    }                                                                           \
} while (0)

#define LOADF(P, BASE, S) do {                                                  \
    const uint32_t _ua = 2 * (S) + kha;                                         \
    const uint32_t _ub = 2 * (S) + khb;                                         \
    _Pragma("unroll")                                                           \
    for (int _i = 0; _i < 4; _i++)                                              \
        ldsm_x4(af[P][_i], (BASE) + aB[_i] + ((_ua ^ a7[_i]) << 4));            \
    _Pragma("unroll")                                                           \
    for (int _q = 0; _q < 2; _q++)                                              \
        ldsm_x4(bf[P][_q], (BASE) + B_OFF + bB[_q] + ((_ub ^ b7[_q]) << 4));    \
} while (0)

#define MMA16(P) do {                                                           \
    _Pragma("unroll")                                                           \
    for (int _i = 0; _i < 4; _i++)                                              \
        _Pragma("unroll")                                                       \
        for (int _f = 0; _f < 4; _f++)                                          \
            mma16816h(acc[_i][_f], af[P][_i], &bf[P][_f >> 1][(_f & 1) * 2]);   \
} while (0)

    __syncthreads();

    for (int t = 0; t < TSTEP; t++) {
        const __half* __restrict__ hin = g_hA[t & 1];
        __half* __restrict__ hout = g_hA[(t & 1) ^ 1];

#pragma unroll
        for (int i = 0; i < 4; i++)
#pragma unroll
            for (int f = 0; f < 4; f++)
#pragma unroll
                for (int v = 0; v < 4; v++) acc[i][f][v] = 0.0f;

        // prologue: chunks 0, 1
        ISSUE_CP(hin, 0, 0); CPA_COMMIT();
        ISSUE_CP(hin, 1, 1); CPA_COMMIT();
        CPA_WAIT1();
        __syncthreads();
        LOADF(0, smem_base, 0);

        int buf = 0;
        for (int c = 0; c < 8; c++) {
            if (c <= 5) { ISSUE_CP(hin, c + 2, (c + 2) % NBUF); CPA_COMMIT(); }
            const uint32_t base = smem_base + buf * BUFSZ;
            // s = 0 (frags already in P=0)
            LOADF(1, base, 1);
            MMA16(0);
            // s = 1
            LOADF(0, base, 2);
            MMA16(1);
            // s = 2
            LOADF(1, base, 3);
            MMA16(0);
            // s = 3 -> overlap with next buffer's first load
            if (c <= 5)      { CPA_WAIT1(); __syncthreads(); }
            else if (c == 6) { CPA_WAIT0(); __syncthreads(); }
            buf = (buf + 1 == NBUF) ? 0 : buf + 1;
            if (c < 7) LOADF(0, smem_base + buf * BUFSZ, 0);
            MMA16(1);
        }

        // ---- register-local fused LSTM cell epilogue ----
        // thread owns rows rbase + i*16 + rh*8 (i=0..3, rh=0..1),
        // hcols hcol_g, hcol_g+1, with all 4 gates in acc[i][*][rh*2 + {0,1}].
#pragma unroll
        for (int i = 0; i < 4; i++) {
#pragma unroll
            for (int rh = 0; rh < 2; rh++) {
                const int m = rbase + i * 16 + rh * 8;
                const int b = bm * 128 + m;
                const float* xgp = g_xg + (size_t)b * GDIM + hcol_g;
                float2 xi = *(const float2*)(xgp);
                float2 xf = *(const float2*)(xgp + 512);
                float2 xgv = *(const float2*)(xgp + 1024);
                float2 xo = *(const float2*)(xgp + 1536);
                const int v0 = rh * 2;
                float gi0 = acc[i][0][v0] + xi.x,  gi1 = acc[i][0][v0 + 1] + xi.y;
                float gf0 = acc[i][1][v0] + xf.x,  gf1 = acc[i][1][v0 + 1] + xf.y;
                float gg0 = acc[i][2][v0] + xgv.x, gg1 = acc[i][2][v0 + 1] + xgv.y;
                float go0 = acc[i][3][v0] + xo.x,  go1 = acc[i][3][v0 + 1] + xo.y;
                const int ci = (i * 2 + rh) * 256 + tid;
                float2 c2 = cS2[ci];
                float cn0 = sigm(gf0) * c2.x + sigm(gi0) * tanh_fast(gg0);
                float cn1 = sigm(gf1) * c2.y + sigm(gi1) * tanh_fast(gg1);
                cS2[ci] = make_float2(cn0, cn1);
                float hn0 = sigm(go0) * tanh_fast(cn0);
                float hn1 = sigm(go1) * tanh_fast(cn1);
                st_cs_f32x2(g_hs + ((size_t)b * TSTEP + t) * HDIM + hcol_g, hn0, hn1);
                __half2 hh = __floats2half2_rn(hn0, hn1);
                *(__half2*)(hout + (size_t)b * HDIM + hcol_g) = hh;
            }
        }

        // ---- grid barrier: h(t+1) must be globally visible ----
        if (t < TSTEP - 1) {
            __threadfence();
            __syncthreads();
            if (tid == 0) {
                atomicAdd(&g_bar, 1u);
                const unsigned target = (unsigned)NCTA * (unsigned)(t + 1);
                while (*(volatile unsigned*)&g_bar < target) { }
            }
            __syncthreads();
        }
    }
#undef ISSUE_CP
#undef LOADF
#undef MMA16
}

// -------- fc: out = relu(hs @ fc_w.T + fc_b) --------------------------------
__global__ __launch_bounds__(256)
void fc_kernel(const float* __restrict__ fc_w,
               const float* __restrict__ fc_b,
               float* __restrict__ out) {
    __shared__ float hsS[16][514];
    const size_t row0 = (size_t)blockIdx.x * 16;
    const int tid = threadIdx.x;

#pragma unroll
    for (int it = 0; it < 16; it++) {
        int i = tid + it * 256;
        int row = i >> 8;
        int cc = (i & 255) * 2;
        float2 v = ld_cs_f32x2(g_hs + (row0 + row) * HDIM + cc);
        *(float2*)&hsS[row][cc] = v;
    }
    __syncthreads();

    const int r = tid & 15;
    const int v0 = (tid >> 4) * 4;
    ull acc[4] = {0ull, 0ull, 0ull, 0ull};
    const float* w0 = fc_w + (size_t)v0 * HDIM;

#pragma unroll 8
    for (int k = 0; k < HDIM; k += 2) {
        ull a = *(const ull*)&hsS[r][k];
        acc[0] = ffma2(a, *(const ull*)(w0 + k),        acc[0]);
        acc[1] = ffma2(a, *(const ull*)(w0 + 512 + k),  acc[1]);
        acc[2] = ffma2(a, *(const ull*)(w0 + 1024 + k), acc[2]);
        acc[3] = ffma2(a, *(const ull*)(w0 + 1536 + k), acc[3]);
    }
#pragma unroll
    for (int jj = 0; jj < 4; jj++) {
        float2 s = up2(acc[jj]);
        float v = s.x + s.y + fc_b[v0 + jj];
        out[(row0 + r) * VDIM + v0 + jj] = fmaxf(v, 0.0f);
    }
}

// ---------------- launch ----------------------------------------------------
extern "C" void kernel_launch(void* const* d_in, const int* in_sizes, int n_in,
                              void* d_out, int out_size) {
    const float* z    = (const float*)d_in[0];
    const float* w_ih = (const float*)d_in[1];
    const float* w_hh = (const float*)d_in[2];
    const float* b_ih = (const float*)d_in[3];
    const float* b_hh = (const float*)d_in[4];
    const float* fc_w = (const float*)d_in[5];
    const float* fc_b = (const float*)d_in[6];
    float* out = (float*)d_out;

    cudaFuncSetAttribute(step_persist, cudaFuncAttributeMaxDynamicSharedMemorySize, SMEM_TOTAL);

    init_kernel<<<(BATCH * HDIM + 255) / 256, 256>>>();
    wprep_kernel<<<(16 * 128 * HDIM + 255) / 256, 256>>>(w_hh);
    pre_kernel<<<dim3(16, 16), 256>>>(z, w_ih, b_ih, b_hh);
    step_persist<<<NCTA, 256, SMEM_TOTAL>>>();
    fc_kernel<<<(BATCH * TSTEP) / 16, 256>>>(fc_w, fc_b, out);
}